// round 3
// baseline (speedup 1.0000x reference)
#include <cuda_runtime.h>
#include <math.h>

// Problem dims
constexpr int Bb  = 8;
constexpr int Ss  = 256;
constexpr int Cc  = 256;
constexpr int Vk  = 64;
constexpr int NBS = Bb * Ss;   // 2048 rows of ctx
constexpr int NN  = Cc * Vk;   // 16384 = flattened (j,k)

using u64 = unsigned long long;

// Scratch (device globals: allocation-free per harness rules)
__device__ float g_W2[(size_t)Cc * Cc * Vk];   // W with linmul folded on diagonal (16.8 MB)
__device__ float g_tmp[(size_t)NBS * NN];      // stage-1 result (134 MB)
__device__ float g_Arow[NBS * Vk];             // per-(b,z) additive term
__device__ float g_Beta[NBS * Vk];             // per-(b,s) additive term (+ all biases except lin1_b)

// ---- packed f32x2 helpers (FFMA2: 2 fp32 FMAs per issue slot) -------------
__device__ __forceinline__ void ffma2(u64 &c, u64 a, u64 b) {
    asm("fma.rn.f32x2 %0, %1, %2, %0;" : "+l"(c) : "l"(a), "l"(b));
}
__device__ __forceinline__ u64 dup2(float v) {
    u64 r; asm("mov.b64 %0, {%1, %1};" : "=l"(r) : "f"(v)); return r;
}
__device__ __forceinline__ float2 unpack2(u64 v) {
    float2 f; asm("mov.b64 {%0, %1}, %2;" : "=f"(f.x), "=f"(f.y) : "l"(v)); return f;
}

// ---------------------------------------------------------------------------
// W2[i,j,k] = W[i,j,k] + (i==j) * linmul_w[k,j]
// ---------------------------------------------------------------------------
__global__ void k_w2(const float* __restrict__ W, const float* __restrict__ lmw) {
    int idx4 = blockIdx.x * 256 + threadIdx.x;
    float4 w = ((const float4*)W)[idx4];
    int e0 = idx4 * 4;
    int k0 = e0 & 63;
    int j  = (e0 >> 6) & 255;
    int i  = e0 >> 14;
    if (i == j) {
        w.x += lmw[(k0 + 0) * Cc + j];
        w.y += lmw[(k0 + 1) * Cc + j];
        w.z += lmw[(k0 + 2) * Cc + j];
        w.w += lmw[(k0 + 3) * Cc + j];
    }
    ((float4*)g_W2)[idx4] = w;
}

// ---------------------------------------------------------------------------
// Arow / Beta per-row GEMVs (small)
// ---------------------------------------------------------------------------
__global__ void k_rowcol(const float* __restrict__ ctx,
                         const float* __restrict__ l1w, const float* __restrict__ l1b,
                         const float* __restrict__ l2w, const float* __restrict__ l2b,
                         const float* __restrict__ lmb,
                         const float* __restrict__ ldw, const float* __restrict__ ldb,
                         const float* __restrict__ bias) {
    __shared__ float xs[Cc];
    int r = blockIdx.x;
    int t = threadIdx.x;                 // 128 threads
    for (int c = t; c < Cc; c += 128) xs[c] = ctx[r * Cc + c];
    __syncthreads();
    if (t < 64) {
        int k = t;
        float acc = 0.f;
        #pragma unroll 8
        for (int c = 0; c < Cc; ++c)
            acc = fmaf(xs[c], l1w[k * Cc + c] + ldw[k * Cc + c], acc);
        g_Arow[r * Vk + k] = acc + l1b[k];
    } else {
        int k = t - 64;
        float acc = 0.f;
        #pragma unroll 8
        for (int c = 0; c < Cc; ++c)
            acc = fmaf(xs[c], l2w[k * Cc + c] - ldw[k * Cc + c], acc);
        g_Beta[r * Vk + k] = acc + l2b[k] + lmb[k] + ldb[k] + bias[k];
    }
}

// ---------------------------------------------------------------------------
// K1: g_tmp(2048 x 16384) = ctx(2048 x 256) @ g_W2(256 x 16384)
// 128x128x16 tiles, 256 threads, 8x8 per thread via FFMA2 (m-paired accs)
// B stored in smem pre-duplicated as (b,b) u64 so mainloop is LDS+FFMA2 only.
// ---------------------------------------------------------------------------
__global__ __launch_bounds__(256, 2) void k_gemm1(const float* __restrict__ A) {
    constexpr int BM = 128, BN = 128, BK = 16, NT = Cc / BK;
    __shared__ float As[2][BK][BM];      // 16 KB
    __shared__ u64   Bsd[2][BK][BN];     // 32 KB (duplicated lanes)

    const int tid = threadIdx.x;
    const int tr  = tid >> 4;            // 0..15
    const int tc  = tid & 15;            // 0..15
    const int rowBase = blockIdx.y * BM;
    const int colBase = blockIdx.x * BN;

    u64 acc[4][8];                       // acc[p][n] packs rows (2p,2p+1), col n
    #pragma unroll
    for (int p = 0; p < 4; ++p)
        #pragma unroll
        for (int n = 0; n < 8; ++n) acc[p][n] = 0ull;

    float4 ra[2], rb[2];

    // prologue: tile 0
    #pragma unroll
    for (int q = 0; q < 2; ++q) {
        int s = tid + q * 256;
        ra[q] = *(const float4*)&A[(size_t)(rowBase + (s >> 2)) * Cc + ((s & 3) << 2)];
        rb[q] = *(const float4*)&g_W2[(size_t)(s >> 5) * NN + colBase + ((s & 31) << 2)];
    }
    #pragma unroll
    for (int q = 0; q < 2; ++q) {
        int s = tid + q * 256;
        int rA = s >> 2, cA = (s & 3) << 2;
        As[0][cA + 0][rA] = ra[q].x;
        As[0][cA + 1][rA] = ra[q].y;
        As[0][cA + 2][rA] = ra[q].z;
        As[0][cA + 3][rA] = ra[q].w;
        int rB = s >> 5, cB = (s & 31) << 2;
        *(ulonglong2*)&Bsd[0][rB][cB]     = make_ulonglong2(dup2(rb[q].x), dup2(rb[q].y));
        *(ulonglong2*)&Bsd[0][rB][cB + 2] = make_ulonglong2(dup2(rb[q].z), dup2(rb[q].w));
    }
    __syncthreads();

    int buf = 0;
    for (int t = 0; t < NT; ++t) {
        if (t + 1 < NT) {
            #pragma unroll
            for (int q = 0; q < 2; ++q) {
                int s = tid + q * 256;
                ra[q] = *(const float4*)&A[(size_t)(rowBase + (s >> 2)) * Cc + (t + 1) * BK + ((s & 3) << 2)];
                rb[q] = *(const float4*)&g_W2[(size_t)((t + 1) * BK + (s >> 5)) * NN + colBase + ((s & 31) << 2)];
            }
        }
        #pragma unroll
        for (int kk = 0; kk < BK; ++kk) {
            ulonglong2 a01 = *(const ulonglong2*)&As[buf][kk][tr * 8];
            ulonglong2 a23 = *(const ulonglong2*)&As[buf][kk][tr * 8 + 4];
            u64 a[4] = {a01.x, a01.y, a23.x, a23.y};
            ulonglong2 b01 = *(const ulonglong2*)&Bsd[buf][kk][tc * 8];
            ulonglong2 b23 = *(const ulonglong2*)&Bsd[buf][kk][tc * 8 + 2];
            ulonglong2 b45 = *(const ulonglong2*)&Bsd[buf][kk][tc * 8 + 4];
            ulonglong2 b67 = *(const ulonglong2*)&Bsd[buf][kk][tc * 8 + 6];
            u64 b[8] = {b01.x, b01.y, b23.x, b23.y, b45.x, b45.y, b67.x, b67.y};
            #pragma unroll
            for (int p = 0; p < 4; ++p)
                #pragma unroll
                for (int n = 0; n < 8; ++n)
                    ffma2(acc[p][n], a[p], b[n]);
        }
        if (t + 1 < NT) {
            int nb = buf ^ 1;
            #pragma unroll
            for (int q = 0; q < 2; ++q) {
                int s = tid + q * 256;
                int rA = s >> 2, cA = (s & 3) << 2;
                As[nb][cA + 0][rA] = ra[q].x;
                As[nb][cA + 1][rA] = ra[q].y;
                As[nb][cA + 2][rA] = ra[q].z;
                As[nb][cA + 3][rA] = ra[q].w;
                int rB = s >> 5, cB = (s & 31) << 2;
                *(ulonglong2*)&Bsd[nb][rB][cB]     = make_ulonglong2(dup2(rb[q].x), dup2(rb[q].y));
                *(ulonglong2*)&Bsd[nb][rB][cB + 2] = make_ulonglong2(dup2(rb[q].z), dup2(rb[q].w));
            }
            __syncthreads();
            buf = nb;
        }
    }

    #pragma unroll
    for (int p = 0; p < 4; ++p) {
        float r0[8], r1[8];
        #pragma unroll
        for (int n = 0; n < 8; ++n) {
            float2 f = unpack2(acc[p][n]);
            r0[n] = f.x; r1[n] = f.y;
        }
        size_t off0 = (size_t)(rowBase + tr * 8 + 2 * p) * NN + colBase + tc * 8;
        size_t off1 = off0 + NN;
        *(float4*)&g_tmp[off0]     = make_float4(r0[0], r0[1], r0[2], r0[3]);
        *(float4*)&g_tmp[off0 + 4] = make_float4(r0[4], r0[5], r0[6], r0[7]);
        *(float4*)&g_tmp[off1]     = make_float4(r1[0], r1[1], r1[2], r1[3]);
        *(float4*)&g_tmp[off1 + 4] = make_float4(r1[4], r1[5], r1[6], r1[7]);
    }
}

// ---------------------------------------------------------------------------
// K2: per (b,s): out(256x64) = tanh( ctx[b](256x256) @ g_tmp[b,s](256x64)
//                                    + Arow[b,z,:] + Beta[b,s,:] )
// 256x64x16 tiles, 256 threads, 8x8 per thread via FFMA2
// ---------------------------------------------------------------------------
__global__ __launch_bounds__(256, 2) void k_gemm2(const float* __restrict__ ctx,
                                                  float* __restrict__ out) {
    constexpr int BM = 256, BN = 64, BK = 16, NT = Cc / BK;
    __shared__ float As[2][BK][BM];      // 32 KB
    __shared__ u64   Bsd[2][BK][BN];     // 16 KB (duplicated lanes)
    __shared__ float beta_s[Vk];

    const int tid = threadIdx.x;
    const int tr  = tid >> 3;            // 0..31 (z-tile)
    const int tc  = tid & 7;             // 0..7  (k-tile)
    const int bs  = blockIdx.x;          // b*S+s
    const int b   = bs >> 8;

    const float* Ab = ctx + (size_t)b * Ss * Cc;
    const float* Bm = g_tmp + (size_t)bs * NN;

    if (tid < Vk) beta_s[tid] = g_Beta[bs * Vk + tid];

    u64 acc[4][8];
    #pragma unroll
    for (int p = 0; p < 4; ++p)
        #pragma unroll
        for (int n = 0; n < 8; ++n) acc[p][n] = 0ull;

    float4 ra[4], rb;

    // prologue: tile 0
    #pragma unroll
    for (int q = 0; q < 4; ++q) {
        int s = tid + q * 256;
        ra[q] = *(const float4*)&Ab[(size_t)(s >> 2) * Cc + ((s & 3) << 2)];
    }
    rb = *(const float4*)&Bm[(size_t)(tid >> 4) * Vk + ((tid & 15) << 2)];
    #pragma unroll
    for (int q = 0; q < 4; ++q) {
        int s = tid + q * 256;
        int rA = s >> 2, cA = (s & 3) << 2;
        As[0][cA + 0][rA] = ra[q].x;
        As[0][cA + 1][rA] = ra[q].y;
        As[0][cA + 2][rA] = ra[q].z;
        As[0][cA + 3][rA] = ra[q].w;
    }
    {
        int rB = tid >> 4, cB = (tid & 15) << 2;
        *(ulonglong2*)&Bsd[0][rB][cB]     = make_ulonglong2(dup2(rb.x), dup2(rb.y));
        *(ulonglong2*)&Bsd[0][rB][cB + 2] = make_ulonglong2(dup2(rb.z), dup2(rb.w));
    }
    __syncthreads();

    int buf = 0;
    for (int t = 0; t < NT; ++t) {
        if (t + 1 < NT) {
            #pragma unroll
            for (int q = 0; q < 4; ++q) {
                int s = tid + q * 256;
                ra[q] = *(const float4*)&Ab[(size_t)(s >> 2) * Cc + (t + 1) * BK + ((s & 3) << 2)];
            }
            rb = *(const float4*)&Bm[(size_t)((t + 1) * BK + (tid >> 4)) * Vk + ((tid & 15) << 2)];
        }
        #pragma unroll
        for (int kk = 0; kk < BK; ++kk) {
            ulonglong2 a01 = *(const ulonglong2*)&As[buf][kk][tr * 8];
            ulonglong2 a23 = *(const ulonglong2*)&As[buf][kk][tr * 8 + 4];
            u64 a[4] = {a01.x, a01.y, a23.x, a23.y};
            ulonglong2 b01 = *(const ulonglong2*)&Bsd[buf][kk][tc * 8];
            ulonglong2 b23 = *(const ulonglong2*)&Bsd[buf][kk][tc * 8 + 2];
            ulonglong2 b45 = *(const ulonglong2*)&Bsd[buf][kk][tc * 8 + 4];
            ulonglong2 b67 = *(const ulonglong2*)&Bsd[buf][kk][tc * 8 + 6];
            u64 b[8] = {b01.x, b01.y, b23.x, b23.y, b45.x, b45.y, b67.x, b67.y};
            #pragma unroll
            for (int p = 0; p < 4; ++p)
                #pragma unroll
                for (int n = 0; n < 8; ++n)
                    ffma2(acc[p][n], a[p], b[n]);
        }
        if (t + 1 < NT) {
            int nb = buf ^ 1;
            #pragma unroll
            for (int q = 0; q < 4; ++q) {
                int s = tid + q * 256;
                int rA = s >> 2, cA = (s & 3) << 2;
                As[nb][cA + 0][rA] = ra[q].x;
                As[nb][cA + 1][rA] = ra[q].y;
                As[nb][cA + 2][rA] = ra[q].z;
                As[nb][cA + 3][rA] = ra[q].w;
            }
            int rB = tid >> 4, cB = (tid & 15) << 2;
            *(ulonglong2*)&Bsd[nb][rB][cB]     = make_ulonglong2(dup2(rb.x), dup2(rb.y));
            *(ulonglong2*)&Bsd[nb][rB][cB + 2] = make_ulonglong2(dup2(rb.z), dup2(rb.w));
            __syncthreads();
            buf = nb;
        }
    }

    // epilogue: + Arow[b,z,k] + Beta[b,s,k], tanh, store
    #pragma unroll
    for (int p = 0; p < 4; ++p) {
        float r0[8], r1[8];
        #pragma unroll
        for (int n = 0; n < 8; ++n) {
            float2 f = unpack2(acc[p][n]);
            r0[n] = f.x; r1[n] = f.y;
        }
        int z0 = tr * 8 + 2 * p;
        #pragma unroll
        for (int h = 0; h < 2; ++h) {
            int z = z0 + h;
            float* rr = h ? r1 : r0;
            size_t arOff = (size_t)(b * Ss + z) * Vk + tc * 8;
            float4 ar0 = *(const float4*)&g_Arow[arOff];
            float4 ar1 = *(const float4*)&g_Arow[arOff + 4];
            float4 o0, o1;
            o0.x = tanhf(rr[0] + ar0.x + beta_s[tc * 8 + 0]);
            o0.y = tanhf(rr[1] + ar0.y + beta_s[tc * 8 + 1]);
            o0.z = tanhf(rr[2] + ar0.z + beta_s[tc * 8 + 2]);
            o0.w = tanhf(rr[3] + ar0.w + beta_s[tc * 8 + 3]);
            o1.x = tanhf(rr[4] + ar1.x + beta_s[tc * 8 + 4]);
            o1.y = tanhf(rr[5] + ar1.y + beta_s[tc * 8 + 5]);
            o1.z = tanhf(rr[6] + ar1.z + beta_s[tc * 8 + 6]);
            o1.w = tanhf(rr[7] + ar1.w + beta_s[tc * 8 + 7]);
            size_t oOff = ((size_t)bs * Ss + z) * Vk + tc * 8;
            *(float4*)&out[oOff]     = o0;
            *(float4*)&out[oOff + 4] = o1;
        }
    }
}

// ---------------------------------------------------------------------------
extern "C" void kernel_launch(void* const* d_in, const int* in_sizes, int n_in,
                              void* d_out, int out_size) {
    const float* ctx       = (const float*)d_in[0];
    const float* W         = (const float*)d_in[1];
    const float* bias      = (const float*)d_in[2];
    const float* lin1_w    = (const float*)d_in[3];
    const float* lin1_b    = (const float*)d_in[4];
    const float* lin2_w    = (const float*)d_in[5];
    const float* lin2_b    = (const float*)d_in[6];
    const float* linmul_w  = (const float*)d_in[7];
    const float* linmul_b  = (const float*)d_in[8];
    const float* lindiff_w = (const float*)d_in[9];
    const float* lindiff_b = (const float*)d_in[10];
    float* out = (float*)d_out;

    k_w2<<<(Cc * Cc * Vk) / (256 * 4), 256>>>(W, linmul_w);
    k_rowcol<<<NBS, 128>>>(ctx, lin1_w, lin1_b, lin2_w, lin2_b,
                           linmul_b, lindiff_w, lindiff_b, bias);
    k_gemm1<<<dim3(NN / 128, NBS / 128), 256>>>(ctx);
    k_gemm2<<<NBS, 256>>>(ctx, out);
}

// round 5
// speedup vs baseline: 3.3315x; 3.3315x over previous
#include <cuda_runtime.h>
#include <cuda_fp16.h>
#include <math.h>
#include <stdint.h>

using u32 = unsigned int;

constexpr int Cc = 256, Vk = 64, NBS = 2048, NN = 16384;

// Scratch (device globals; allocation-free)
__device__ __half g_ch[NBS * Cc], g_cl[NBS * Cc];                   // ctx split
__device__ __half g_Wh[(size_t)NN * Cc], g_Wl[(size_t)NN * Cc];     // W2' [n'=(k,j)][i]
__device__ __half g_th[(size_t)NBS * Vk * Cc];                      // tmp hi [bs][k][j]
__device__ __half g_tl[(size_t)NBS * Vk * Cc];                      // tmp lo
__device__ float g_Arow[NBS * Vk], g_Beta[NBS * Vk];

// ---------------- helpers ----------------
__device__ __forceinline__ u32 smem_u32(const void* p) {
    u32 a;
    asm("{ .reg .u64 t; cvta.to.shared.u64 t, %1; cvt.u32.u64 %0, t; }" : "=r"(a) : "l"(p));
    return a;
}
#define SWZ(o) ((o) ^ (((o) >> 3) & 0x70))

__device__ __forceinline__ void cpa16(u32 dst, const void* src) {
    asm volatile("cp.async.cg.shared.global [%0], [%1], 16;" :: "r"(dst), "l"(src));
}
#define CP_COMMIT() asm volatile("cp.async.commit_group;")
#define CP_WAIT0()  asm volatile("cp.async.wait_group 0;")

__device__ __forceinline__ void ldmA(u32 addr, u32& a0, u32& a1, u32& a2, u32& a3) {
    asm volatile("ldmatrix.sync.aligned.m8n8.x4.shared.b16 {%0,%1,%2,%3}, [%4];"
                 : "=r"(a0), "=r"(a1), "=r"(a2), "=r"(a3) : "r"(addr));
}
__device__ __forceinline__ void ldmB(u32 addr, u32& b0, u32& b1) {
    asm volatile("ldmatrix.sync.aligned.m8n8.x2.shared.b16 {%0,%1}, [%2];"
                 : "=r"(b0), "=r"(b1) : "r"(addr));
}
__device__ __forceinline__ void mma16816(float* c, const u32* a, const u32* b) {
    asm volatile("mma.sync.aligned.m16n8k16.row.col.f32.f16.f16.f32 "
                 "{%0,%1,%2,%3}, {%4,%5,%6,%7}, {%8,%9}, {%0,%1,%2,%3};"
                 : "+f"(c[0]), "+f"(c[1]), "+f"(c[2]), "+f"(c[3])
                 : "r"(a[0]), "r"(a[1]), "r"(a[2]), "r"(a[3]), "r"(b[0]), "r"(b[1]));
}

// ---------------- prep kernels ----------------
__global__ void k_split_ctx(const float* __restrict__ ctx) {
    int i = blockIdx.x * 256 + threadIdx.x;
    float x = ctx[i];
    __half h = __float2half_rn(x);
    g_ch[i] = h;
    g_cl[i] = __float2half_rn(x - __half2float(h));
}

// W2'[(k*256+j)][i] = W[i][j*64+k] + (i==j)*lmw[k*256+j], split hi/lo
__global__ void k_prep_w(const float* __restrict__ W, const float* __restrict__ lmw) {
    __shared__ float tile[32][33];
    int tx = threadIdx.x, ty = threadIdx.y;          // (32, 8)
    int n0 = blockIdx.x * 32, i0 = blockIdx.y * 32;
    #pragma unroll
    for (int q = 0; q < 4; ++q) {
        int i = i0 + ty + q * 8, n = n0 + tx;
        float v = W[(size_t)i * NN + n];
        int j = n >> 6, k = n & 63;
        if (i == j) v += lmw[k * Cc + j];
        tile[ty + q * 8][tx] = v;
    }
    __syncthreads();
    #pragma unroll
    for (int q = 0; q < 4; ++q) {
        int n = n0 + ty + q * 8, i = i0 + tx;
        float v = tile[tx][ty + q * 8];
        int j = n >> 6, k = n & 63;
        size_t np = (size_t)(k * 256 + j) * Cc + i;
        __half h = __float2half_rn(v);
        g_Wh[np] = h;
        g_Wl[np] = __float2half_rn(v - __half2float(h));
    }
}

__global__ void k_rowcol(const float* __restrict__ ctx,
                         const float* __restrict__ l1w, const float* __restrict__ l1b,
                         const float* __restrict__ l2w, const float* __restrict__ l2b,
                         const float* __restrict__ lmb,
                         const float* __restrict__ ldw, const float* __restrict__ ldb,
                         const float* __restrict__ bias) {
    __shared__ float xs[Cc];
    int r = blockIdx.x, t = threadIdx.x;
    for (int c = t; c < Cc; c += 128) xs[c] = ctx[r * Cc + c];
    __syncthreads();
    if (t < 64) {
        int k = t; float acc = 0.f;
        #pragma unroll 8
        for (int c = 0; c < Cc; ++c) acc = fmaf(xs[c], l1w[k * Cc + c] + ldw[k * Cc + c], acc);
        g_Arow[r * Vk + k] = acc + l1b[k];
    } else {
        int k = t - 64; float acc = 0.f;
        #pragma unroll 8
        for (int c = 0; c < Cc; ++c) acc = fmaf(xs[c], l2w[k * Cc + c] - ldw[k * Cc + c], acc);
        g_Beta[r * Vk + k] = acc + l2b[k] + lmb[k] + ldb[k] + bias[k];
    }
}

// ---------------- stage 1: tmp = ctx @ W2' (HMMA fp16 split) ----------------
// grid (128 n'-tiles, 16 m-tiles), 256 thr. CTA 128x128, BK=64, 4 chunks.
// smem buf: Ah 0 | Al 16K | Bh 32K | Bl 48K  (64K per buf, 2 bufs)
__global__ __launch_bounds__(256) void k_mma1() {
    extern __shared__ char sm[];
    const u32 smb = smem_u32(sm);
    const int tid = threadIdx.x, lane = tid & 31, wid = tid >> 5;
    const int wm = wid >> 2, wn = wid & 3;           // 2 x 4 warps; warp tile 64x32
    const int rowBase = blockIdx.y * 128;
    const int colBase = blockIdx.x * 128;

    auto load = [&](int c, int p) {
        u32 d = smb + p * 65536;
        const char* sA_h = (const char*)g_ch + ((size_t)rowBase * Cc + c * 64) * 2;
        const char* sA_l = (const char*)g_cl + ((size_t)rowBase * Cc + c * 64) * 2;
        const char* sB_h = (const char*)g_Wh + ((size_t)colBase * Cc + c * 64) * 2;
        const char* sB_l = (const char*)g_Wl + ((size_t)colBase * Cc + c * 64) * 2;
        #pragma unroll
        for (int q = 0; q < 4; ++q) {
            int s = tid + q * 256;
            int r = s >> 3, co = (s & 7) * 16;
            u32 sw = SWZ(r * 128 + co);
            cpa16(d + sw,         sA_h + (size_t)r * 512 + co);
            cpa16(d + 16384 + sw, sA_l + (size_t)r * 512 + co);
            cpa16(d + 32768 + sw, sB_h + (size_t)r * 512 + co);
            cpa16(d + 49152 + sw, sB_l + (size_t)r * 512 + co);
        }
    };

    float acc[4][4][4];
    #pragma unroll
    for (int t = 0; t < 4; ++t)
        #pragma unroll
        for (int u = 0; u < 4; ++u)
            #pragma unroll
            for (int e = 0; e < 4; ++e) acc[t][u][e] = 0.f;

    load(0, 0); CP_COMMIT();

    for (int c = 0; c < 4; ++c) {
        CP_WAIT0();
        __syncthreads();
        if (c < 3) { load(c + 1, (c + 1) & 1); CP_COMMIT(); }
        u32 bufA = smb + (c & 1) * 65536;
        u32 bufB = bufA + 32768;
        #pragma unroll
        for (int ks = 0; ks < 4; ++ks) {
            u32 ah[4][4], al[4][4], bh[4][2], bl[4][2];
            int arow = wm * 64 + (lane & 15);
            int acol = ks * 32 + (lane >> 4) * 16;
            #pragma unroll
            for (int t = 0; t < 4; ++t) {
                u32 sw = SWZ((arow + t * 16) * 128 + acol);
                ldmA(bufA + sw,         ah[t][0], ah[t][1], ah[t][2], ah[t][3]);
                ldmA(bufA + 16384 + sw, al[t][0], al[t][1], al[t][2], al[t][3]);
            }
            int brow = wn * 32 + (lane & 7);
            int bcol = ks * 32 + ((lane >> 3) & 1) * 16;
            #pragma unroll
            for (int u = 0; u < 4; ++u) {
                u32 sw = SWZ((brow + u * 8) * 128 + bcol);
                ldmB(bufB + sw,         bh[u][0], bh[u][1]);
                ldmB(bufB + 16384 + sw, bl[u][0], bl[u][1]);
            }
            #pragma unroll
            for (int t = 0; t < 4; ++t)
                #pragma unroll
                for (int u = 0; u < 4; ++u) {
                    mma16816(acc[t][u], ah[t], bh[u]);
                    mma16816(acc[t][u], ah[t], bl[u]);
                    mma16816(acc[t][u], al[t], bh[u]);
                }
        }
        __syncthreads();
    }

    // epilogue: n' = k*256 + j ; CTA covers one k, half of j
    const int k = blockIdx.x >> 1;
    const int jb = (blockIdx.x & 1) * 128;
    #pragma unroll
    for (int t = 0; t < 4; ++t)
        #pragma unroll
        for (int u = 0; u < 4; ++u) {
            int j0 = jb + wn * 32 + u * 8 + (lane & 3) * 2;
            #pragma unroll
            for (int h = 0; h < 2; ++h) {
                int m = rowBase + wm * 64 + t * 16 + (lane >> 2) + h * 8;
                float v0 = acc[t][u][h * 2], v1 = acc[t][u][h * 2 + 1];
                __half h0 = __float2half_rn(v0), h1 = __float2half_rn(v1);
                __half2 hv; hv.x = h0; hv.y = h1;
                __half2 lv;
                lv.x = __float2half_rn(v0 - __half2float(h0));
                lv.y = __float2half_rn(v1 - __half2float(h1));
                size_t off = ((size_t)m * 64 + k) * 256 + j0;
                *(__half2*)(g_th + off) = hv;
                *(__half2*)(g_tl + off) = lv;
            }
        }
}

// ---------------- stage 2: out = tanh(ctx_b @ tmp_bs^T + Arow + Beta) -------
// grid (256 s, 2 ztile, 8 b), 256 thr. CTA 128(z) x 64(k), K=j=256, BK=64.
// smem buf: Ah 0 | Al 16K | Bh 32K | Bl 40K  (48K per buf, 2 bufs)
__global__ __launch_bounds__(256) void k_mma2(float* __restrict__ out) {
    extern __shared__ char sm[];
    __shared__ float beta_sm[Vk];
    const u32 smb = smem_u32(sm);
    const int tid = threadIdx.x, lane = tid & 31, wid = tid >> 5;
    const int wm = wid >> 1, wn = wid & 1;           // 4 x 2 warps; warp tile 32x32
    const int s = blockIdx.x, zBase = blockIdx.y * 128, b = blockIdx.z;
    const int bs = b * 256 + s;

    if (tid < Vk) beta_sm[tid] = g_Beta[bs * Vk + tid];

    auto load = [&](int c, int p) {
        u32 d = smb + p * 49152;
        const char* sA_h = (const char*)g_ch + (((size_t)(b * 256 + zBase)) * Cc + c * 64) * 2;
        const char* sA_l = (const char*)g_cl + (((size_t)(b * 256 + zBase)) * Cc + c * 64) * 2;
        const char* sB_h = (const char*)g_th + (((size_t)bs * 64) * Cc + c * 64) * 2;
        const char* sB_l = (const char*)g_tl + (((size_t)bs * 64) * Cc + c * 64) * 2;
        #pragma unroll
        for (int q = 0; q < 4; ++q) {
            int ss = tid + q * 256;
            int r = ss >> 3, co = (ss & 7) * 16;
            u32 sw = SWZ(r * 128 + co);
            cpa16(d + sw,         sA_h + (size_t)r * 512 + co);
            cpa16(d + 16384 + sw, sA_l + (size_t)r * 512 + co);
        }
        #pragma unroll
        for (int q = 0; q < 2; ++q) {
            int ss = tid + q * 256;
            int r = ss >> 3, co = (ss & 7) * 16;
            u32 sw = SWZ(r * 128 + co);
            cpa16(d + 32768 + sw, sB_h + (size_t)r * 512 + co);
            cpa16(d + 40960 + sw, sB_l + (size_t)r * 512 + co);
        }
    };

    float acc[2][4][4];
    #pragma unroll
    for (int t = 0; t < 2; ++t)
        #pragma unroll
        for (int u = 0; u < 4; ++u)
            #pragma unroll
            for (int e = 0; e < 4; ++e) acc[t][u][e] = 0.f;

    load(0, 0); CP_COMMIT();

    for (int c = 0; c < 4; ++c) {
        CP_WAIT0();
        __syncthreads();
        if (c < 3) { load(c + 1, (c + 1) & 1); CP_COMMIT(); }
        u32 bufA = smb + (c & 1) * 49152;
        u32 bufB = bufA + 32768;
        #pragma unroll
        for (int ks = 0; ks < 4; ++ks) {
            u32 ah[2][4], al[2][4], bh[4][2], bl[4][2];
            int arow = wm * 32 + (lane & 15);
            int acol = ks * 32 + (lane >> 4) * 16;
            #pragma unroll
            for (int t = 0; t < 2; ++t) {
                u32 sw = SWZ((arow + t * 16) * 128 + acol);
                ldmA(bufA + sw,         ah[t][0], ah[t][1], ah[t][2], ah[t][3]);
                ldmA(bufA + 16384 + sw, al[t][0], al[t][1], al[t][2], al[t][3]);
            }
            int brow = wn * 32 + (lane & 7);
            int bcol = ks * 32 + ((lane >> 3) & 1) * 16;
            #pragma unroll
            for (int u = 0; u < 4; ++u) {
                u32 sw = SWZ((brow + u * 8) * 128 + bcol);
                ldmB(bufB + sw,        bh[u][0], bh[u][1]);
                ldmB(bufB + 8192 + sw, bl[u][0], bl[u][1]);
            }
            #pragma unroll
            for (int t = 0; t < 2; ++t)
                #pragma unroll
                for (int u = 0; u < 4; ++u) {
                    mma16816(acc[t][u], ah[t], bh[u]);
                    mma16816(acc[t][u], ah[t], bl[u]);
                    mma16816(acc[t][u], al[t], bh[u]);
                }
        }
        __syncthreads();
    }

    // epilogue
    #pragma unroll
    for (int t = 0; t < 2; ++t)
        #pragma unroll
        for (int u = 0; u < 4; ++u) {
            int k0 = wn * 32 + u * 8 + (lane & 3) * 2;
            #pragma unroll
            for (int h = 0; h < 2; ++h) {
                int z = zBase + wm * 32 + t * 16 + (lane >> 2) + h * 8;
                float2 ar = *(const float2*)&g_Arow[(size_t)(b * 256 + z) * Vk + k0];
                float2 o;
                o.x = tanhf(acc[t][u][h * 2]     + ar.x + beta_sm[k0]);
                o.y = tanhf(acc[t][u][h * 2 + 1] + ar.y + beta_sm[k0 + 1]);
                *(float2*)&out[(((size_t)bs * 256 + z) * Vk) + k0] = o;
            }
        }
}

// ---------------------------------------------------------------------------
extern "C" void kernel_launch(void* const* d_in, const int* in_sizes, int n_in,
                              void* d_out, int out_size) {
    const float* ctx       = (const float*)d_in[0];
    const float* W         = (const float*)d_in[1];
    const float* bias      = (const float*)d_in[2];
    const float* lin1_w    = (const float*)d_in[3];
    const float* lin1_b    = (const float*)d_in[4];
    const float* lin2_w    = (const float*)d_in[5];
    const float* lin2_b    = (const float*)d_in[6];
    const float* linmul_w  = (const float*)d_in[7];
    const float* linmul_b  = (const float*)d_in[8];
    const float* lindiff_w = (const float*)d_in[9];
    const float* lindiff_b = (const float*)d_in[10];
    float* out = (float*)d_out;

    static bool attr_set = false;
    if (!attr_set) {
        cudaFuncSetAttribute(k_mma1, cudaFuncAttributeMaxDynamicSharedMemorySize, 131072);
        cudaFuncSetAttribute(k_mma2, cudaFuncAttributeMaxDynamicSharedMemorySize, 98304);
        attr_set = true;
    }

    k_split_ctx<<<NBS * Cc / 256, 256>>>(ctx);
    k_prep_w<<<dim3(NN / 32, Cc / 32), dim3(32, 8)>>>(W, linmul_w);
    k_rowcol<<<NBS, 128>>>(ctx, lin1_w, lin1_b, lin2_w, lin2_b,
                           linmul_b, lindiff_w, lindiff_b, bias);
    k_mma1<<<dim3(128, 16), 256, 131072>>>();
    k_mma2<<<dim3(256, 2, 8), 256, 98304>>>(out);
}